// round 15
// baseline (speedup 1.0000x reference)
#include <cuda_runtime.h>
#include <cstdint>

// Problem constants
#define BQ   4
#define NP   16384
#define PQ   2048
#define CF   64
#define NS   32
#define TILE 2048
#define QPW  4     // queries per warp
#define NTHR 128   // 4 warps, 16 queries per block
#define LCAP 64    // per-lane candidate capacity

// Scratch: final (masked) neighbor indices per (b,p,s)
__device__ int g_idx[BQ * PQ * NS];
// Scratch: transposed features (B, N, C)
__device__ float g_ft[BQ * NP * CF];
// Scratch: per-(query,lane) candidate buffers
__device__ unsigned long long g_cand[(size_t)BQ * PQ * 32 * LCAP];

__device__ __forceinline__ unsigned long long warpMinULL(unsigned long long v) {
#pragma unroll
    for (int off = 16; off; off >>= 1) {
        unsigned long long o = __shfl_xor_sync(0xffffffffu, v, off);
        if (o < v) v = o;
    }
    return v;
}

__device__ __forceinline__ unsigned fkey(float f) {
    unsigned b = __float_as_uint(f);
    return (b & 0x80000000u) ? ~b : (b | 0x80000000u);
}

// ===== FROZEN reference-bitwise arithmetic (validated rel_err == 0.0) =====
// q2 chain (queries, scalar left-assoc):   rn( rn(x^2 + y^2) + z^2 )
__device__ __forceinline__ float sq_L(float x, float y, float z) {
    return __fadd_rn(__fadd_rn(__fmul_rn(x, x), __fmul_rn(y, y)),
                     __fmul_rn(z, z));
}
// p2 chain (points, SIMD split-half):      rn( rn(x^2 + z^2) + y^2 )
__device__ __forceinline__ float sq_H(float x, float y, float z) {
    return __fadd_rn(__fadd_rn(__fmul_rn(x, x), __fmul_rn(z, z)),
                     __fmul_rn(y, y));
}
// cross: ascending-k fma chain; d2 = rn( rn(q2+p2) - 2*cross )
__device__ __forceinline__ float d2_ref(float qx, float qy, float qz, float q2,
                                        float x, float y, float z) {
    float p2 = sq_H(x, y, z);
    float cr = __fmaf_rn(qz, z, __fmaf_rn(qy, y, __fmul_rn(qx, x)));
    return __fadd_rn(__fadd_rn(q2, p2), __fmul_rn(-2.0f, cr));
}
// ==========================================================================

// ---------------------------------------------------------------------------
// Kernel 1: KNN with radius filtering. 128 threads = 4 warps, QPW=4 ->
// 16 queries/block, 512 blocks (single wave, all resident).
// Per-lane private candidate buffers, predicated stores: no ballot, no
// divergent branch, no atomics. Candidate order is irrelevant to selection.
// Tile stores (-2x,-2y,-2z,p2_H); -2 scaling is exact and commutes with every
// rounding of the fma chain -> m2cross is -2*cross bitwise.
// ---------------------------------------------------------------------------
__global__ void __launch_bounds__(NTHR)
knn_kernel(const float* __restrict__ xyz, const float* __restrict__ nxyz) {
    __shared__ float4 tile[TILE];

    // keep iff d2 <= 0.25 + 2^-25 (== fl(sqrt(d2)) <= 0.5)
    const float KEEP = __uint_as_float(0x3E800001u);

    const int tid = threadIdx.x;
    const int lane = tid & 31;
    const int warp = tid >> 5;
    const int qbase = blockIdx.x * (NTHR / 32 * QPW) + warp * QPW;
    const int b = qbase / PQ;
    const float* __restrict__ Xb = xyz + (size_t)b * NP * 3;

    float qx[QPW], qy[QPW], qz[QPW], q2[QPW];
    int cnt[QPW];
    unsigned long long* bufq[QPW];
#pragma unroll
    for (int i = 0; i < QPW; i++) {
        int gq = qbase + i;
        qx[i] = nxyz[gq * 3 + 0];
        qy[i] = nxyz[gq * 3 + 1];
        qz[i] = nxyz[gq * 3 + 2];
        q2[i] = sq_L(qx[i], qy[i], qz[i]);     // queries: left-assoc
        cnt[i] = 0;
        bufq[i] = g_cand + ((size_t)gq * 32 + lane) * LCAP;
    }

    // ---- filtered scan over all N points, tiled through shared memory ----
    for (int t0 = 0; t0 < NP; t0 += TILE) {
        if (t0) __syncthreads();           // previous tile fully consumed
        for (int j = tid; j < TILE; j += NTHR) {
            int gi = t0 + j;
            float x = Xb[gi * 3 + 0];
            float y = Xb[gi * 3 + 1];
            float z = Xb[gi * 3 + 2];
            tile[j] = make_float4(-2.0f * x, -2.0f * y, -2.0f * z,
                                  sq_H(x, y, z));  // points: split-half
        }
        __syncthreads();

        for (int j = lane; j < TILE; j += 32) {
            float4 pt = tile[j];
            unsigned idx = (unsigned)(t0 + j);
#pragma unroll
            for (int qi = 0; qi < QPW; qi++) {
                // m2cross = -2 * cross, bitwise, ascending-k fma chain (A)
                float m2cross = __fmaf_rn(qz[qi], pt.z,
                                 __fmaf_rn(qy[qi], pt.y,
                                  __fmul_rn(qx[qi], pt.x)));
                float s = __fadd_rn(q2[qi], pt.w);   // rn(q2 + p2)
                float d2 = __fadd_rn(s, m2cross);    // rn(s - 2*cross)
                bool pass = (d2 <= KEEP);
                int pos = min(cnt[qi], LCAP - 1);
                if (pass)
                    bufq[qi][pos] =
                        ((unsigned long long)fkey(d2) << 32) | idx;
                cnt[qi] += pass;
            }
        }
    }
    __syncwarp();

    // ---- per-query selection: 32 smallest (d2, idx) lexicographic ----
#pragma unroll 1
    for (int qi = 0; qi < QPW; qi++) {
        const int gq = qbase + qi;
        const int myc = cnt[qi];                       // per-lane count
        const int ctot = __reduce_add_sync(0xffffffffu, myc);
        const bool ovf = __any_sync(0xffffffffu, myc >= LCAP);
        unsigned long long mine = 0;

        if (ovf) {
            // conservative overflow: exact 32 rounds over global xyz.
            unsigned long long prev = 0;
            for (int r = 0; r < NS; r++) {
                unsigned long long best = ~0ull;
                for (int i = lane; i < NP; i += 32) {
                    float d2 = d2_ref(qx[qi], qy[qi], qz[qi], q2[qi],
                                      Xb[i * 3 + 0], Xb[i * 3 + 1], Xb[i * 3 + 2]);
                    unsigned long long e =
                        ((unsigned long long)fkey(d2) << 32) | (unsigned)i;
                    if (e > prev && e < best) best = e;
                }
                unsigned long long w = warpMinULL(best);
                prev = w;
                if (lane == r) mine = w;
            }
        } else if (ctot == 0) {
            // no point within radius: every sample = overall nearest neighbor
            unsigned long long best = ~0ull;
            for (int i = lane; i < NP; i += 32) {
                float d2 = d2_ref(qx[qi], qy[qi], qz[qi], q2[qi],
                                  Xb[i * 3 + 0], Xb[i * 3 + 1], Xb[i * 3 + 2]);
                unsigned long long e =
                    ((unsigned long long)fkey(d2) << 32) | (unsigned)i;
                if (e < best) best = e;
            }
            mine = warpMinULL(best);       // same for all lanes
        } else {
            const unsigned long long* __restrict__ buf = bufq[qi];
            const int rounds = ctot < NS ? ctot : NS;
            unsigned long long prev = 0, first = 0;
            for (int r = 0; r < rounds; r++) {
                unsigned long long best = ~0ull;
                for (int i = 0; i < myc; i++) {        // lane-local scan
                    unsigned long long e = buf[i];
                    if (e > prev && e < best) best = e;
                }
                unsigned long long w = warpMinULL(best);
                prev = w;
                if (r == 0) first = w;
                if (lane == r) mine = w;
            }
            if (lane >= rounds) mine = first;   // masked samples -> idx[0]
        }
        g_idx[gq * NS + lane] = (int)(mine & 0xffffffffu);
    }
}

// ---------------------------------------------------------------------------
// Kernel 2: feature transpose (B,C,N) -> (B,N,C). Classic 32x32 smem tile.
// ---------------------------------------------------------------------------
__global__ void __launch_bounds__(256)
transpose_kernel(const float* __restrict__ feat) {
    __shared__ float t[32][33];
    const int n0 = blockIdx.x * 32;
    const int c0 = (blockIdx.y & 1) * 32;
    const int b  = blockIdx.y >> 1;
    const float* __restrict__ fb = feat + (size_t)b * CF * NP;
    for (int i = threadIdx.y; i < 32; i += 8)
        t[i][threadIdx.x] = fb[(size_t)(c0 + i) * NP + n0 + threadIdx.x];
    __syncthreads();
    float* __restrict__ ft = g_ft + (size_t)b * NP * CF;
    for (int i = threadIdx.y; i < 32; i += 8)
        ft[(size_t)(n0 + i) * CF + c0 + threadIdx.x] = t[threadIdx.x][i];
}

// ---------------------------------------------------------------------------
// Kernel 3: gather from transposed features. One block per (b,p).
// ---------------------------------------------------------------------------
__global__ void __launch_bounds__(256)
gather_kernel(const float* __restrict__ xyz, const float* __restrict__ nxyz,
              float* __restrict__ outA, float* __restrict__ outB, int writeB) {
    const int bp = blockIdx.x;             // 0..8191
    const int b = bp >> 11;
    const int p = bp & 2047;
    const int tid = threadIdx.x;
    const int s = tid & 31;
    const int cg = tid >> 5;

    __shared__ int sidx[NS];
    __shared__ float sg[3][NS];
    __shared__ float srow[NS][CF + 1];     // +1: odd stride, conflict-free

    if (tid < NS) {
        int i = g_idx[bp * NS + tid];
        sidx[tid] = i;
        const float* pt = xyz + ((size_t)b * NP + i) * 3;
        const float* q = nxyz + (size_t)bp * 3;
        sg[0][tid] = pt[0] - q[0];
        sg[1][tid] = pt[1] - q[1];
        sg[2][tid] = pt[2] - q[2];
    }
    __syncthreads();

    {
        int r = tid >> 3, part = tid & 7;
        const float4* src = (const float4*)(g_ft +
                            ((size_t)b * NP + sidx[r]) * CF) + part * 2;
        float4 v0 = src[0];
        float4 v1 = src[1];
        float* dst = &srow[r][part * 8];
        dst[0] = v0.x; dst[1] = v0.y; dst[2] = v0.z; dst[3] = v0.w;
        dst[4] = v1.x; dst[5] = v1.y; dst[6] = v1.z; dst[7] = v1.w;
    }
    __syncthreads();

    for (int ch = cg; ch < 67; ch += 8) {
        float v = (ch < 3) ? sg[ch][s] : srow[s][ch - 3];
        outA[(((size_t)b * 67 + ch) * PQ + p) * NS + s] = v;
    }
    if (writeB && cg < 3) {
        outB[(((size_t)b * 3 + cg) * PQ + p) * NS + s] = sg[cg][s];
    }
}

// ---------------------------------------------------------------------------
extern "C" void kernel_launch(void* const* d_in, const int* in_sizes, int n_in,
                              void* d_out, int out_size) {
    const float* xyz  = (const float*)d_in[0];   // (B,N,3)
    const float* nxyz = (const float*)d_in[1];   // (B,NPOINT,3)
    const float* feat = (const float*)d_in[2];   // (B,C,N)
    float* out = (float*)d_out;

    const size_t segA = (size_t)BQ * 67 * PQ * NS;   // new_features
    const size_t segB = (size_t)BQ * 3 * PQ * NS;    // grouped_xyz
    const int writeB = ((size_t)out_size >= segA + segB) ? 1 : 0;

    transpose_kernel<<<dim3(NP / 32, 2 * BQ), dim3(32, 8)>>>(feat);
    knn_kernel<<<(BQ * PQ) / (NTHR / 32 * QPW), NTHR>>>(xyz, nxyz);
    gather_kernel<<<BQ * PQ, 256>>>(xyz, nxyz, out, out + segA, writeB);
}

// round 16
// speedup vs baseline: 2.8313x; 2.8313x over previous
#include <cuda_runtime.h>
#include <cstdint>

// Problem constants
#define BQ   4
#define NP   16384
#define PQ   2048
#define CF   64
#define NS   32
#define CAP  768
#define G    21
#define NCELL (G * G * G)
#define ORG  (-5.25f)

// Scratch
__device__ int g_idx[BQ * PQ * NS];
__device__ float g_ft[BQ * NP * CF];
__device__ unsigned long long g_cand[(size_t)BQ * PQ * CAP];
__device__ int g_ccnt[BQ * NCELL];            // counts, then fill cursors
__device__ int g_cellstart[BQ * (NCELL + 1)];
__device__ float4 g_pts[BQ * NP];             // (-2x,-2y,-2z,p2_H), binned
__device__ int g_pidx[BQ * NP];               // original point index

__device__ __forceinline__ unsigned long long warpMinULL(unsigned long long v) {
#pragma unroll
    for (int off = 16; off; off >>= 1) {
        unsigned long long o = __shfl_xor_sync(0xffffffffu, v, off);
        if (o < v) v = o;
    }
    return v;
}

__device__ __forceinline__ unsigned fkey(float f) {
    unsigned b = __float_as_uint(f);
    return (b & 0x80000000u) ? ~b : (b | 0x80000000u);
}

__device__ __forceinline__ int cell1(float v) {
    int c = (int)floorf((v - ORG) * 2.0f);
    return min(max(c, 0), G - 1);
}

// ===== FROZEN reference-bitwise arithmetic (validated rel_err == 0.0) =====
__device__ __forceinline__ float sq_L(float x, float y, float z) {
    return __fadd_rn(__fadd_rn(__fmul_rn(x, x), __fmul_rn(y, y)),
                     __fmul_rn(z, z));
}
__device__ __forceinline__ float sq_H(float x, float y, float z) {
    return __fadd_rn(__fadd_rn(__fmul_rn(x, x), __fmul_rn(z, z)),
                     __fmul_rn(y, y));
}
__device__ __forceinline__ float d2_ref(float qx, float qy, float qz, float q2,
                                        float x, float y, float z) {
    float p2 = sq_H(x, y, z);
    float cr = __fmaf_rn(qz, z, __fmaf_rn(qy, y, __fmul_rn(qx, x)));
    return __fadd_rn(__fadd_rn(q2, p2), __fmul_rn(-2.0f, cr));
}
// ==========================================================================

// ---- binning ----
__global__ void zero_kernel() {
    int i = blockIdx.x * blockDim.x + threadIdx.x;
    if (i < BQ * NCELL) g_ccnt[i] = 0;
}

__global__ void count_kernel(const float* __restrict__ xyz) {
    int i = blockIdx.x * blockDim.x + threadIdx.x;
    if (i >= BQ * NP) return;
    float x = xyz[i * 3 + 0], y = xyz[i * 3 + 1], z = xyz[i * 3 + 2];
    int b = i >> 14;
    int cell = (cell1(z) * G + cell1(y)) * G + cell1(x);
    atomicAdd(&g_ccnt[b * NCELL + cell], 1);
}

__global__ void scan_kernel() {   // one block per batch, 1024 threads
    int b = blockIdx.x;
    int t = threadIdx.x;
    __shared__ int ps[1024];
    int base = t * 10;
    int loc[10];
    int sum = 0;
#pragma unroll
    for (int k = 0; k < 10; k++) {
        int c = base + k;
        int v = (c < NCELL) ? g_ccnt[b * NCELL + c] : 0;
        loc[k] = sum;
        sum += v;
    }
    ps[t] = sum;
    __syncthreads();
    for (int off = 1; off < 1024; off <<= 1) {
        int v = (t >= off) ? ps[t - off] : 0;
        __syncthreads();
        ps[t] += v;
        __syncthreads();
    }
    int pre = (t == 0) ? 0 : ps[t - 1];
#pragma unroll
    for (int k = 0; k < 10; k++) {
        int c = base + k;
        if (c < NCELL) {
            int s = pre + loc[k];
            g_cellstart[b * (NCELL + 1) + c] = s;
            g_ccnt[b * NCELL + c] = s;       // becomes fill cursor
        }
    }
    if (t == 0) g_cellstart[b * (NCELL + 1) + NCELL] = NP;
}

__global__ void scatter_kernel(const float* __restrict__ xyz) {
    int i = blockIdx.x * blockDim.x + threadIdx.x;
    if (i >= BQ * NP) return;
    float x = xyz[i * 3 + 0], y = xyz[i * 3 + 1], z = xyz[i * 3 + 2];
    int b = i >> 14, j = i & (NP - 1);
    int cell = (cell1(z) * G + cell1(y)) * G + cell1(x);
    int pos = atomicAdd(&g_ccnt[b * NCELL + cell], 1);
    g_pts[b * NP + pos] = make_float4(-2.0f * x, -2.0f * y, -2.0f * z,
                                      sq_H(x, y, z));
    g_pidx[b * NP + pos] = j;
}

// ---------------------------------------------------------------------------
// KNN: one warp per query; 27-cell neighborhood = 9 contiguous runs.
// Ballot-compacted candidates into per-query global buffer (R14 machinery).
// ---------------------------------------------------------------------------
__global__ void __launch_bounds__(256)
knn_kernel(const float* __restrict__ xyz, const float* __restrict__ nxyz) {
    const float KEEP = __uint_as_float(0x3E800001u);

    const int lane = threadIdx.x & 31;
    const int warp = threadIdx.x >> 5;
    const unsigned ltmask = (1u << lane) - 1u;
    const int gq = blockIdx.x * 8 + warp;
    const int b = gq >> 11;
    const float* __restrict__ Xb = xyz + (size_t)b * NP * 3;
    const int* __restrict__ cs = g_cellstart + b * (NCELL + 1);
    const float4* __restrict__ pts = g_pts + b * NP;
    const int* __restrict__ pix = g_pidx + b * NP;
    unsigned long long* __restrict__ buf = g_cand + (size_t)gq * CAP;

    const float qx = nxyz[gq * 3 + 0];
    const float qy = nxyz[gq * 3 + 1];
    const float qz = nxyz[gq * 3 + 2];
    const float q2 = sq_L(qx, qy, qz);

    const int cx = cell1(qx), cy = cell1(qy), cz = cell1(qz);
    const int x0 = max(cx - 1, 0), x1 = min(cx + 1, G - 1);
    const int y0 = max(cy - 1, 0), y1 = min(cy + 1, G - 1);
    const int z0 = max(cz - 1, 0), z1 = min(cz + 1, G - 1);

    int cnt = 0;
    for (int zz = z0; zz <= z1; zz++)
        for (int yy = y0; yy <= y1; yy++) {
            int row = (zz * G + yy) * G;
            int s = cs[row + x0];
            int e = cs[row + x1 + 1];
            for (int base = s; base < e; base += 32) {
                int i = base + lane;
                int i2 = min(i, e - 1);
                float4 pt = pts[i2];
                float m2cross = __fmaf_rn(qz, pt.z,
                                 __fmaf_rn(qy, pt.y,
                                  __fmul_rn(qx, pt.x)));
                float ss = __fadd_rn(q2, pt.w);
                float d2 = __fadd_rn(ss, m2cross);
                bool pass = (i < e) && (d2 <= KEEP);
                unsigned m = __ballot_sync(0xffffffffu, pass);
                if (m) {
                    int pos = cnt + __popc(m & ltmask);
                    if (pass && pos < CAP)
                        buf[pos] = ((unsigned long long)fkey(d2) << 32) |
                                   (unsigned)pix[i2];
                    cnt += __popc(m);
                }
            }
        }
    __syncwarp();

    // ---- selection: 32 smallest (d2, idx) lexicographic ----
    unsigned long long mine = 0;
    if (cnt > CAP) {
        unsigned long long prev = 0;
        for (int r = 0; r < NS; r++) {
            unsigned long long best = ~0ull;
            for (int i = lane; i < NP; i += 32) {
                float d2 = d2_ref(qx, qy, qz, q2,
                                  Xb[i * 3 + 0], Xb[i * 3 + 1], Xb[i * 3 + 2]);
                unsigned long long e =
                    ((unsigned long long)fkey(d2) << 32) | (unsigned)i;
                if (e > prev && e < best) best = e;
            }
            unsigned long long w = warpMinULL(best);
            prev = w;
            if (lane == r) mine = w;
        }
    } else if (cnt == 0) {
        unsigned long long best = ~0ull;
        for (int i = lane; i < NP; i += 32) {
            float d2 = d2_ref(qx, qy, qz, q2,
                              Xb[i * 3 + 0], Xb[i * 3 + 1], Xb[i * 3 + 2]);
            unsigned long long e =
                ((unsigned long long)fkey(d2) << 32) | (unsigned)i;
            if (e < best) best = e;
        }
        mine = warpMinULL(best);
    } else {
        const int rounds = cnt < NS ? cnt : NS;
        unsigned long long prev = 0, first = 0;
        for (int r = 0; r < rounds; r++) {
            unsigned long long best = ~0ull;
            for (int i = lane; i < cnt; i += 32) {
                unsigned long long e = buf[i];
                if (e > prev && e < best) best = e;
            }
            unsigned long long w = warpMinULL(best);
            prev = w;
            if (r == 0) first = w;
            if (lane == r) mine = w;
        }
        if (lane >= rounds) mine = first;
    }
    g_idx[gq * NS + lane] = (int)(mine & 0xffffffffu);
}

// ---- transpose (B,C,N) -> (B,N,C) ----
__global__ void __launch_bounds__(256)
transpose_kernel(const float* __restrict__ feat) {
    __shared__ float t[32][33];
    const int n0 = blockIdx.x * 32;
    const int c0 = (blockIdx.y & 1) * 32;
    const int b  = blockIdx.y >> 1;
    const float* __restrict__ fb = feat + (size_t)b * CF * NP;
    for (int i = threadIdx.y; i < 32; i += 8)
        t[i][threadIdx.x] = fb[(size_t)(c0 + i) * NP + n0 + threadIdx.x];
    __syncthreads();
    float* __restrict__ ft = g_ft + (size_t)b * NP * CF;
    for (int i = threadIdx.y; i < 32; i += 8)
        ft[(size_t)(n0 + i) * CF + c0 + threadIdx.x] = t[threadIdx.x][i];
}

// ---- gather ----
__global__ void __launch_bounds__(256)
gather_kernel(const float* __restrict__ xyz, const float* __restrict__ nxyz,
              float* __restrict__ outA, float* __restrict__ outB, int writeB) {
    const int bp = blockIdx.x;
    const int b = bp >> 11;
    const int p = bp & 2047;
    const int tid = threadIdx.x;
    const int s = tid & 31;
    const int cg = tid >> 5;

    __shared__ int sidx[NS];
    __shared__ float sg[3][NS];
    __shared__ float srow[NS][CF + 1];

    if (tid < NS) {
        int i = g_idx[bp * NS + tid];
        sidx[tid] = i;
        const float* pt = xyz + ((size_t)b * NP + i) * 3;
        const float* q = nxyz + (size_t)bp * 3;
        sg[0][tid] = pt[0] - q[0];
        sg[1][tid] = pt[1] - q[1];
        sg[2][tid] = pt[2] - q[2];
    }
    __syncthreads();

    {
        int r = tid >> 3, part = tid & 7;
        const float4* src = (const float4*)(g_ft +
                            ((size_t)b * NP + sidx[r]) * CF) + part * 2;
        float4 v0 = src[0];
        float4 v1 = src[1];
        float* dst = &srow[r][part * 8];
        dst[0] = v0.x; dst[1] = v0.y; dst[2] = v0.z; dst[3] = v0.w;
        dst[4] = v1.x; dst[5] = v1.y; dst[6] = v1.z; dst[7] = v1.w;
    }
    __syncthreads();

    for (int ch = cg; ch < 67; ch += 8) {
        float v = (ch < 3) ? sg[ch][s] : srow[s][ch - 3];
        outA[(((size_t)b * 67 + ch) * PQ + p) * NS + s] = v;
    }
    if (writeB && cg < 3) {
        outB[(((size_t)b * 3 + cg) * PQ + p) * NS + s] = sg[cg][s];
    }
}

// ---------------------------------------------------------------------------
extern "C" void kernel_launch(void* const* d_in, const int* in_sizes, int n_in,
                              void* d_out, int out_size) {
    const float* xyz  = (const float*)d_in[0];   // (B,N,3)
    const float* nxyz = (const float*)d_in[1];   // (B,NPOINT,3)
    const float* feat = (const float*)d_in[2];   // (B,C,N)
    float* out = (float*)d_out;

    const size_t segA = (size_t)BQ * 67 * PQ * NS;
    const size_t segB = (size_t)BQ * 3 * PQ * NS;
    const int writeB = ((size_t)out_size >= segA + segB) ? 1 : 0;

    zero_kernel<<<(BQ * NCELL + 255) / 256, 256>>>();
    count_kernel<<<(BQ * NP + 255) / 256, 256>>>(xyz);
    scan_kernel<<<BQ, 1024>>>();
    scatter_kernel<<<(BQ * NP + 255) / 256, 256>>>(xyz);
    transpose_kernel<<<dim3(NP / 32, 2 * BQ), dim3(32, 8)>>>(feat);
    knn_kernel<<<(BQ * PQ) / 8, 256>>>(xyz, nxyz);
    gather_kernel<<<BQ * PQ, 256>>>(xyz, nxyz, out, out + segA, writeB);
}